// round 10
// baseline (speedup 1.0000x reference)
#include <cuda_runtime.h>
#include <cuda_bf16.h>

// GAT: 4 GATConv layers (3 heads x 12 out), concat for layers 0-2 (relu), mean
// for layer 3, then two small linear layers -> [N, 6].
//
//  1) CSR build (atomic-free scatter via rank = hist atomic return value).
//  2) t0: initial transform x -> h0/als0/ald0.
//  3) A0..A2: FEATURE-PER-LANE warp aggregation of layer l FUSED with the
//     transform of layer l+1 (node-local matvec from registers/smem) writing
//     double-buffered h/als/ald. Launch boundary = global barrier for gathers.
//  4) A3: aggregation + head-mean + lin1 + lin2 -> d_out.
//  Softmax max-subtraction dropped: exact (all segments have a self-loop,
//  logits O(1)).

#define HEADS 3
#define OUTF  12
#define F     36            // HEADS*OUTF
#define HPAD  40            // padded h row stride (160B)
#define NMAX  50000
#define EMAX  800000
#define TOTMAX (EMAX + NMAX)

// ---------------- device scratch (static; no allocation) ----------------
__device__ float g_h[2][NMAX * HPAD];    // double-buffered transformed features
__device__ float g_als[2][NMAX * HEADS];
__device__ float g_ald[2][NMAX * HEADS];
__device__ int   g_deg[NMAX];       // zero at entry (zero-init / reset each pass)
__device__ int   g_rank[EMAX];      // intra-node rank of each edge
__device__ int   g_rowstart[NMAX + 1];
__device__ int   g_csrsrc[TOTMAX + 32];   // +32 pad (zero-init) for chunked over-read
__device__ int   g_blocksums[128];

// ---------------- CSR build ----------------
__global__ void k_hist(const int* __restrict__ dst, int E) {
    int base = blockIdx.x * 1024 + threadIdx.x;
    #pragma unroll
    for (int k = 0; k < 4; k++) {
        int i = base + k * 256;
        if (i < E) g_rank[i] = atomicAdd(&g_deg[dst[i]], 1);
    }
}

__global__ void k_scan_block(int N) {  // blockDim == 1024
    __shared__ int sh[1024];
    int t = threadIdx.x;
    int idx = blockIdx.x * 1024 + t;
    int v = (idx < N) ? (g_deg[idx] + 1) : 0;   // +1 = self-loop
    sh[t] = v;
    __syncthreads();
    #pragma unroll
    for (int off = 1; off < 1024; off <<= 1) {
        int add = (t >= off) ? sh[t - off] : 0;
        __syncthreads();
        sh[t] += add;
        __syncthreads();
    }
    if (idx < N) g_rowstart[idx] = sh[t];          // per-block inclusive (temp)
    if (t == 1023) g_blocksums[blockIdx.x] = sh[1023];
}

__global__ void k_scan_finish(int N, int TOT, int nb) {
    __shared__ int soff[128];
    int t = threadIdx.x;    // blockDim == 256
    if (t < 128) soff[t] = (t < nb) ? g_blocksums[t] : 0;
    __syncthreads();
    #pragma unroll
    for (int off = 1; off < 128; off <<= 1) {
        int add = 0;
        if (t < 128 && t >= off) add = soff[t - off];
        __syncthreads();
        if (t < 128) soff[t] += add;
        __syncthreads();
    }
    int idx = blockIdx.x * blockDim.x + t;
    if (idx < N) {
        int b = idx >> 10;
        int boff = (b == 0) ? 0 : soff[b - 1];
        int incl = g_rowstart[idx] + boff;
        g_rowstart[idx] = incl - (g_deg[idx] + 1);
        g_deg[idx] = 0;       // reset for next replay
    }
    if (idx == 0) g_rowstart[N] = TOT;
}

// Atomic-free scatter: pos = rowstart[d] + rank; self-loop at rowstart[n+1]-1.
__global__ void k_scatter(const int* __restrict__ src, const int* __restrict__ dst,
                          int E, int N) {
    int base = blockIdx.x * 1024 + threadIdx.x;
    #pragma unroll
    for (int k = 0; k < 4; k++) {
        int i = base + k * 256;
        if (i < E) {
            int d = dst[i];
            g_csrsrc[g_rowstart[d] + g_rank[i]] = src[i];
        } else if (i < E + N) {
            int n = i - E;
            g_csrsrc[g_rowstart[n + 1] - 1] = n;  // self loop
        }
    }
}

// ---------------- initial transform (layer 0): h0 = x @ W0^T ----------------
// Block = 128 threads handling 256 nodes (2 per thread); writes buffer 0.
__global__ void __launch_bounds__(128) k_transform0(
        const float* __restrict__ xin,
        const float* __restrict__ W,
        const float* __restrict__ asrc,
        const float* __restrict__ adst, int N) {
    const int IN = 24;
    __shared__ float sW[F * IN];
    __shared__ float sA[F], sB[F];
    __shared__ float sy[256 * 37];
    int t = threadIdx.x;
    for (int i = t; i < F * IN; i += 128) sW[i] = W[i];
    if (t < F) { sA[t] = asrc[t]; sB[t] = adst[t]; }

    int n0 = blockIdx.x * 256;
    int rows = min(256, N - n0);
    const float* srcbase = xin + (size_t)n0 * IN;
    int avail = rows * IN;
    for (int idx = t; idx < avail; idx += 128) {
        int r = idx / IN, c = idx - r * IN;
        sy[r * 37 + c] = srcbase[idx];
    }
    __syncthreads();

    bool va = (t < rows);
    bool vb = (t + 128 < rows);
    int na = n0 + t, nb2 = n0 + t + 128;
    float ya[IN], yb[IN];
    #pragma unroll
    for (int i = 0; i < IN; i++) ya[i] = va ? sy[t * 37 + i] : 0.f;
    #pragma unroll
    for (int i = 0; i < IN; i++) yb[i] = vb ? sy[(t + 128) * 37 + i] : 0.f;

    float asa[3] = {0.f, 0.f, 0.f}, ada[3] = {0.f, 0.f, 0.f};
    float asb[3] = {0.f, 0.f, 0.f}, adb[3] = {0.f, 0.f, 0.f};

    #pragma unroll
    for (int j = 0; j < F; j++) {
        float ha = 0.f, hb = 0.f;
        #pragma unroll
        for (int i = 0; i < IN; i++) {
            float w = sW[j * IN + i];
            ha += w * ya[i];
            hb += w * yb[i];
        }
        sy[t * 37 + j] = ha;
        sy[(t + 128) * 37 + j] = hb;
        float aj = sA[j], bj = sB[j];
        int hh = j / OUTF;
        asa[hh] += ha * aj; ada[hh] += ha * bj;
        asb[hh] += hb * aj; adb[hh] += hb * bj;
    }
    if (va) {
        #pragma unroll
        for (int hh = 0; hh < 3; hh++) {
            g_als[0][na * 3 + hh] = asa[hh];
            g_ald[0][na * 3 + hh] = ada[hh];
        }
    }
    if (vb) {
        #pragma unroll
        for (int hh = 0; hh < 3; hh++) {
            g_als[0][nb2 * 3 + hh] = asb[hh];
            g_ald[0][nb2 * 3 + hh] = adb[hh];
        }
    }
    __syncthreads();
    int availh = rows * F;
    float* hbase = g_h[0] + (size_t)n0 * HPAD;
    for (int idx = t; idx < availh; idx += 128) {
        int r = idx / F, c = idx - r * F;
        hbase[r * HPAD + c] = sy[r * 37 + c];
    }
}

// ---------------- shared aggregation mainloop ----------------
// Lane f (0..31) owns feature f; lanes 24..27 additionally own 32..35 (head 2
// -> reuse own p/sp). Softmax denominator identical across a head group.
template <int SRC>
__device__ __forceinline__ void agg_mainloop(
        int n, int lane, int h1, bool sec,
        float& acc1, float& acc2, float& sp1) {
    int r0 = g_rowstart[n];
    int r1 = g_rowstart[n + 1];
    float ald1 = g_ald[SRC][n * 3 + h1];
    acc1 = 0.f; acc2 = 0.f; sp1 = 0.f;
    for (int base = r0; base < r1; base += 32) {
        int mysrc = g_csrsrc[base + lane];   // chunk preload (zero-padded tail)
        int cnt = min(32, r1 - base);
        #pragma unroll 4
        for (int j = 0; j < cnt; j++) {
            int s = __shfl_sync(0xFFFFFFFFu, mysrc, j);
            float e = g_als[SRC][s * 3 + h1] + ald1;
            e = fmaxf(e, 0.2f * e);          // leaky relu (slope < 1)
            float p = __expf(e);
            sp1 += p;
            const float* hr = g_h[SRC] + (size_t)s * HPAD;
            acc1 += p * hr[lane];
            if (sec) acc2 += p * hr[32 + (lane - 24)];
        }
    }
}

// ---------------- fused aggregate(l) + transform(l+1) ----------------
// Reads buffer SRC, writes h/als/ald into buffer 1-SRC. Wn is layer l+1's
// weight [36x36]; bias is layer l's bias (concat+relu output).
template <int SRC>
__global__ void __launch_bounds__(256) k_agg_fused(
        const float* __restrict__ bias, int N,
        const float* __restrict__ Wn,
        const float* __restrict__ an_src,
        const float* __restrict__ an_dst) {
    constexpr int DST = 1 - SRC;
    __shared__ float sWT[F * 37];        // transposed next-layer W
    __shared__ float sA[F], sB[F];
    __shared__ float stage[8][40];       // per-warp y staging
    __shared__ float sPA[8][40], sPB[8][40];
    int t = threadIdx.x;
    for (int i = t; i < F * F; i += 256) {
        int j = i / F, k = i - j * F;    // W[j][k]
        sWT[k * 37 + j] = Wn[i];
    }
    if (t < F) { sA[t] = an_src[t]; sB[t] = an_dst[t]; }
    __syncthreads();

    int warp = (blockIdx.x * blockDim.x + t) >> 5;
    int lane = t & 31;
    if (warp >= N) return;
    int n = warp;
    int w = t >> 5;
    int h1 = lane / OUTF;
    bool sec = (lane >= 24) && (lane < 28);

    float acc1, acc2, sp1;
    agg_mainloop<SRC>(n, lane, h1, sec, acc1, acc2, sp1);
    float inv1 = 1.f / (sp1 + 1e-16f);

    // layer-l output (concat + relu), staged for the node-local matvec
    float v = fmaxf(acc1 * inv1 + bias[lane], 0.f);
    stage[w][lane] = v;
    if (sec) stage[w][32 + (lane - 24)] =
        fmaxf(acc2 * inv1 + bias[32 + (lane - 24)], 0.f);
    __syncwarp();

    // transform(l+1): h_j = sum_i WT[i][j] * y_i   (broadcast LDS, no conflicts)
    float hj = 0.f, hj2 = 0.f;
    #pragma unroll
    for (int i = 0; i < F; i++) {
        float yi = stage[w][i];
        hj += sWT[i * 37 + lane] * yi;
        if (sec) hj2 += sWT[i * 37 + 32 + (lane - 24)] * yi;
    }
    float* hout = g_h[DST] + (size_t)n * HPAD;
    hout[lane] = hj;
    if (sec) hout[32 + (lane - 24)] = hj2;

    // attention logits for layer l+1
    float pa = hj * sA[lane], pb = hj * sB[lane];
    if (sec) {
        pa += hj2 * sA[32 + (lane - 24)];
        pb += hj2 * sB[32 + (lane - 24)];
    }
    sPA[w][lane] = pa; sPB[w][lane] = pb;
    __syncwarp();
    if (lane < 3) {
        int j0 = lane * 12;
        int j1 = (lane == 2) ? 32 : (j0 + 12);  // head2 products live in lanes 24..31
        float sa = 0.f, sb2 = 0.f;
        for (int j = j0; j < j1; j++) { sa += sPA[w][j]; sb2 += sPB[w][j]; }
        g_als[DST][n * 3 + lane] = sa;
        g_ald[DST][n * 3 + lane] = sb2;
    }
}

// ---------------- final aggregate: mean over heads + lin1 + lin2 ----------------
template <int SRC>
__global__ void __launch_bounds__(256) k_agg_final(
        const float* __restrict__ bias, int N,
        const float* __restrict__ w1, const float* __restrict__ b1,
        const float* __restrict__ w2, const float* __restrict__ b2,
        float* __restrict__ out) {
    int warp = (blockIdx.x * blockDim.x + threadIdx.x) >> 5;
    int lane = threadIdx.x & 31;
    if (warp >= N) return;
    int n = warp;
    int h1 = lane / OUTF;
    bool sec = (lane >= 24) && (lane < 28);

    float acc1, acc2, sp1;
    agg_mainloop<SRC>(n, lane, h1, sec, acc1, acc2, sp1);
    float inv1 = 1.f / (sp1 + 1e-16f);

    float v1 = acc1 * inv1;              // (head h1, feat lane%12)
    float v2 = acc2 * inv1;              // lanes 24..27: head2 feats 8..11
    float b12 = __shfl_sync(0xFFFFFFFFu, v1, lane + 12);           // head1
    float c24 = __shfl_sync(0xFFFFFFFFu, v1, lane + 24);           // head2 o<8
    float c2  = __shfl_sync(0xFFFFFFFFu, v2, lane + 16);           // head2 o>=8
    float v = 0.f;
    if (lane < OUTF) {
        float c = (lane < 8) ? c24 : c2;
        v = (v1 + b12 + c) * (1.f / 3.f) + bias[lane];
    }
    // lin1: u[lane] = b1[lane] + sum_i v_i * w1[lane*12+i]   (lane < 12)
    float u = (lane < 12) ? b1[lane] : 0.f;
    #pragma unroll
    for (int i = 0; i < 12; i++) {
        float vi = __shfl_sync(0xFFFFFFFFu, v, i);
        if (lane < 12) u += vi * __ldg(&w1[lane * 12 + i]);
    }
    // lin2: o[lane] = b2[lane] + sum_j u_j * w2[lane*12+j]   (lane < 6)
    float o = (lane < 6) ? b2[lane] : 0.f;
    #pragma unroll
    for (int j = 0; j < 12; j++) {
        float uj = __shfl_sync(0xFFFFFFFFu, u, j);
        if (lane < 6) o += uj * __ldg(&w2[lane * 12 + j]);
    }
    if (lane < 6) out[(size_t)n * 6 + lane] = o;
}

// ---------------- launch ----------------
extern "C" void kernel_launch(void* const* d_in, const int* in_sizes, int n_in,
                              void* d_out, int out_size) {
    const float* x  = (const float*)d_in[0];
    const int*   ei = (const int*)d_in[1];
    int E = in_sizes[1] / 2;
    int N = in_sizes[0] / 24;
    if (N > NMAX || E > EMAX) return;
    const int* srcp = ei;
    const int* dstp = ei + E;

    const float* W[4], *AS[4], *AD[4], *B[4];
    for (int l = 0; l < 4; l++) {
        W[l]  = (const float*)d_in[2 + 4 * l];
        AS[l] = (const float*)d_in[3 + 4 * l];
        AD[l] = (const float*)d_in[4 + 4 * l];
        B[l]  = (const float*)d_in[5 + 4 * l];
    }
    const float* lin1w = (const float*)d_in[18];
    const float* lin1b = (const float*)d_in[19];
    const float* lin2w = (const float*)d_in[20];
    const float* lin2b = (const float*)d_in[21];
    float* out = (float*)d_out;

    int TOT = E + N;
    int nb = (N + 1023) / 1024;

    k_hist<<<(E + 1023) / 1024, 256>>>(dstp, E);
    k_scan_block<<<nb, 1024>>>(N);
    k_scan_finish<<<(N + 255) / 256, 256>>>(N, TOT, nb);
    k_scatter<<<(TOT + 1023) / 1024, 256>>>(srcp, dstp, E, N);

    int tgrid = (N + 255) / 256;
    int agrid = (N * 32 + 255) / 256;       // 1 node per warp

    k_transform0<<<tgrid, 128>>>(x, W[0], AS[0], AD[0], N);           // -> buf0
    k_agg_fused<0><<<agrid, 256>>>(B[0], N, W[1], AS[1], AD[1]);      // buf0 -> buf1
    k_agg_fused<1><<<agrid, 256>>>(B[1], N, W[2], AS[2], AD[2]);      // buf1 -> buf0
    k_agg_fused<0><<<agrid, 256>>>(B[2], N, W[3], AS[3], AD[3]);      // buf0 -> buf1
    k_agg_final<1><<<agrid, 256>>>(B[3], N, lin1w, lin1b, lin2w, lin2b, out);
}